// round 9
// baseline (speedup 1.0000x reference)
#include <cuda_runtime.h>
#include <cstdint>

// SoftTree: x[4096,512], gw[512,255], gb[255], pw[64,512,256], pb[64,256]
// out[b,o] = sum_l leafp[b,l] * ((x @ pw[o])[b,l] + pb[o,l])
//
// R9 vs R8: GEMM 256 -> 512 threads (16 warps, 4 warps/SMSP), warp tile
// 32x64, acc 64 regs (R6 retry, but with packed fragment feed: 2 LDS.128 +
// 8 LDS.64 per warp-ks). pwp prep stores coalesced (2x float4).

#define N_BATCH   4096
#define N_IN      512
#define N_OUT     64
#define N_LEAF    256
#define N_GATE    255
#define TREE_DEPTH 8

__device__ float  d_leafp[N_BATCH * N_LEAF];                 // 4 MB
__device__ float4 d_xt2[(N_BATCH / 128) * 16 * 1024];        // 8 MB  (A quads)
__device__ float2 d_pwp[(size_t)N_OUT * 16 * 4096];          // 33.5 MB (B pairs)

__device__ __forceinline__ float rna_tf32(float f) {
    uint32_t u;
    asm("cvt.rna.tf32.f32 %0, %1;" : "=r"(u) : "f"(f));
    return __uint_as_float(u);
}
__device__ __forceinline__ uint32_t smem_u32(const void* p) {
    uint32_t a;
    asm("{ .reg .u64 t; cvta.to.shared.u64 t, %1; cvt.u32.u64 %0, t; }"
        : "=r"(a) : "l"(p));
    return a;
}

#define CP_ASYNC16(dst_u32, src_ptr) \
    asm volatile("cp.async.cg.shared.global [%0], [%1], 16;" \
                 :: "r"(dst_u32), "l"(src_ptr))
#define CP_COMMIT()  asm volatile("cp.async.commit_group;" ::: "memory")
#define CP_WAIT2()   asm volatile("cp.async.wait_group 2;" ::: "memory")

__device__ __forceinline__ void mma_tf32(float* d, const uint32_t* a,
                                         const uint32_t* b) {
    asm volatile(
        "mma.sync.aligned.m16n8k8.row.col.f32.tf32.tf32.f32 "
        "{%0,%1,%2,%3}, {%4,%5,%6,%7}, {%8,%9}, {%0,%1,%2,%3};"
        : "+f"(d[0]), "+f"(d[1]), "+f"(d[2]), "+f"(d[3])
        : "r"(a[0]), "r"(a[1]), "r"(a[2]), "r"(a[3]), "r"(b[0]), "r"(b[1]));
}

// ---------------------------------------------------------------------------
// P0: x -> A-frag quads. Quad (bt,kt,mb,ks,lq,lr):
//   rows b = bt*128 + mb*16 + lq (+8), cols k = kt*32 + ks*8 + lr (+4)
//   float4 = { x[b][k], x[b+8][k], x[b][k+4], x[b+8][k+4] }  (rna)
//   linear = (bt*16+kt)*1024 + (mb*4+ks)*32 + lq*4 + lr
// ---------------------------------------------------------------------------
__global__ __launch_bounds__(256) void xt2_kernel(const float* __restrict__ x) {
    const int kt = blockIdx.x, bt = blockIdx.y;
    #pragma unroll
    for (int it = 0; it < 4; ++it) {
        int qid = it * 256 + threadIdx.x;          // 0..1023
        int mb = qid >> 7, ks = (qid >> 5) & 3, lq = (qid >> 2) & 7, lr = qid & 3;
        int b = bt * 128 + mb * 16 + lq;
        int k = kt * 32 + ks * 8 + lr;
        const float* xb = x + (size_t)b * N_IN + k;
        float4 q;
        q.x = rna_tf32(xb[0]);
        q.y = rna_tf32(xb[8 * N_IN]);
        q.z = rna_tf32(xb[4]);
        q.w = rna_tf32(xb[8 * N_IN + 4]);
        d_xt2[(size_t)(bt * 16 + kt) * 1024 + qid] = q;
    }
}

// ---------------------------------------------------------------------------
// P1: pw -> B-frag pairs.  Pair (o,kt,ks,n,lr):
//   float2 = { pw[o][kt*32+ks*8+lr][n], pw[o][kt*32+ks*8+lr+4][n] } (rna)
//   linear = ((o*16+kt)*4+ks)*1024 + n*4 + lr
// Stores: 4 pairs/thread = 32B contiguous -> 2 coalesced float4 stores.
// ---------------------------------------------------------------------------
__global__ __launch_bounds__(256) void pwp_kernel(const float* __restrict__ pw) {
    const int o = blockIdx.y;
    const int kt = blockIdx.x >> 2, ks = blockIdx.x & 3;
    const int n = threadIdx.x;
    const int k0 = kt * 32 + ks * 8;
    const float* src = pw + ((size_t)o * N_IN + k0) * N_LEAF + n;
    float v[8];
    #pragma unroll
    for (int j = 0; j < 8; ++j) v[j] = rna_tf32(src[j * N_LEAF]);
    float4* dst = reinterpret_cast<float4*>(
        d_pwp + ((size_t)(o * 16 + kt) * 4 + ks) * 1024 + n * 4);
    dst[0] = make_float4(v[0], v[4], v[1], v[5]);
    dst[1] = make_float4(v[2], v[6], v[3], v[7]);
}

// ---------------------------------------------------------------------------
// K2: gates + leaf probabilities (proven)
// ---------------------------------------------------------------------------
#define K1_ROWS 8
__global__ __launch_bounds__(256) void softtree_gates_kernel(
    const float* __restrict__ x, const float* __restrict__ gw,
    const float* __restrict__ gb)
{
    __shared__ float xs[K1_ROWS][N_IN];
    __shared__ float gs[K1_ROWS][N_LEAF];
    const int tid = threadIdx.x;
    const int b0  = blockIdx.x * K1_ROWS;

    {
        const float4* src = reinterpret_cast<const float4*>(x + (size_t)b0 * N_IN);
        float4* dst = reinterpret_cast<float4*>(&xs[0][0]);
        #pragma unroll
        for (int it = 0; it < (K1_ROWS * N_IN / 4) / 256; ++it)
            dst[it * 256 + tid] = src[it * 256 + tid];
    }
    __syncthreads();

    if (tid < N_GATE) {
        float acc[K1_ROWS];
        const float bias = gb[tid];
        #pragma unroll
        for (int r = 0; r < K1_ROWS; ++r) acc[r] = bias;
        #pragma unroll 4
        for (int i = 0; i < N_IN; ++i) {
            float w = gw[i * N_GATE + tid];
            #pragma unroll
            for (int r = 0; r < K1_ROWS; ++r)
                acc[r] = fmaf(xs[r][i], w, acc[r]);
        }
        #pragma unroll
        for (int r = 0; r < K1_ROWS; ++r)
            gs[r][tid] = 1.0f / (1.0f + expf(-acc[r]));
    }
    __syncthreads();

    const int l = tid;
    #pragma unroll
    for (int r = 0; r < K1_ROWS; ++r) {
        float p = 1.0f;
        int index = 1;
        #pragma unroll
        for (int j = 0; j < TREE_DEPTH; ++j) {
            int bit = (l >> (TREE_DEPTH - 1 - j)) & 1;
            float g = gs[r][index - 1];
            p *= bit ? (1.0f - g) : g;
            index = 2 * index + bit;
        }
        d_leafp[(size_t)(b0 + r) * N_LEAF + l] = p;
    }
}

// ---------------------------------------------------------------------------
// K3: tf32 mma.sync GEMM, fragment-order smem, fused epilogue.
// Grid (32 bt, 64 o), 512 threads (16 warps, 4m x 4n), warp tile 32x64.
// Stage = A 16KB + B 32KB; 4-stage ring, 1 barrier/stage.
// ---------------------------------------------------------------------------
#define A_STAGE_F  4096
#define B_STAGE_F  8192
#define STAGE_FLOATS (A_STAGE_F + B_STAGE_F)
#define N_STAGES 4
#define SMEM_FLOATS (N_STAGES * STAGE_FLOATS + 4 * 128)
#define N_KT 16

__global__ __launch_bounds__(512, 1) void softtree_gemm_mma(
    const float* __restrict__ pb, float* __restrict__ out)
{
    extern __shared__ float sm[];
    float* red = sm + N_STAGES * STAGE_FLOATS;   // [4][128]

    const int tid  = threadIdx.x;
    const int lane = tid & 31;
    const int wid  = tid >> 5;
    const int wm   = wid >> 2;          // 0..3 -> 32-row group
    const int wn   = wid & 3;           // 0..3 -> 64-col group
    const int lq   = lane >> 2;         // 0..7
    const int lr   = lane & 3;          // 0..3
    const int o    = blockIdx.y;
    const int bt   = blockIdx.x;
    const int b0   = bt * 128;

    const float4* __restrict__ xa_all = d_xt2 + (size_t)bt * 16 * 1024;
    const float2* __restrict__ bb_all = d_pwp + (size_t)o * 16 * 4096;

    auto load_stage = [&](int kt) {
        const int s = kt & (N_STAGES - 1);
        uint32_t a_base = smem_u32(sm + s * STAGE_FLOATS);
        uint32_t b_base = a_base + A_STAGE_F * 4;
        const float4* xa = xa_all + kt * 1024;
        const float2* bb = bb_all + kt * 4096;
        #pragma unroll
        for (int it = 0; it < 2; ++it) {
            int i = it * 512 + tid;                 // quad 0..1023
            CP_ASYNC16(a_base + (uint32_t)i * 16, xa + i);
        }
        #pragma unroll
        for (int it = 0; it < 4; ++it) {
            int i = it * 512 + tid;                 // 16B granule = 2 pairs
            CP_ASYNC16(b_base + (uint32_t)i * 16, bb + i * 2);
        }
        CP_COMMIT();
    };

    float acc[2][8][4];
    #pragma unroll
    for (int mf = 0; mf < 2; ++mf)
        #pragma unroll
        for (int nf = 0; nf < 8; ++nf)
            #pragma unroll
            for (int e = 0; e < 4; ++e) acc[mf][nf][e] = 0.0f;

    load_stage(0);
    load_stage(1);
    load_stage(2);

    for (int kt = 0; kt < N_KT; ++kt) {
        CP_WAIT2();
        __syncthreads();
        if (kt + 3 < N_KT) load_stage(kt + 3);

        const int s = kt & (N_STAGES - 1);
        const float* Asb = sm + s * STAGE_FLOATS;
        const float* Bsb = Asb + A_STAGE_F;

        #pragma unroll
        for (int ks = 0; ks < 4; ++ks) {
            uint32_t af[2][4], bf[8][2];
            #pragma unroll
            for (int mf = 0; mf < 2; ++mf) {
                const int mb = wm * 2 + mf;
                float4 a4 = *reinterpret_cast<const float4*>(
                    Asb + ((size_t)((mb * 4 + ks) * 32 + lq * 4 + lr)) * 4);
                af[mf][0] = __float_as_uint(a4.x);
                af[mf][1] = __float_as_uint(a4.y);
                af[mf][2] = __float_as_uint(a4.z);
                af[mf][3] = __float_as_uint(a4.w);
            }
            #pragma unroll
            for (int nf = 0; nf < 8; ++nf) {
                const int n = wn * 64 + nf * 8 + lq;
                float2 b2 = *reinterpret_cast<const float2*>(
                    Bsb + ((size_t)((ks * 256 + n) * 4 + lr)) * 2);
                bf[nf][0] = __float_as_uint(b2.x);
                bf[nf][1] = __float_as_uint(b2.y);
            }
            #pragma unroll
            for (int mf = 0; mf < 2; ++mf)
                #pragma unroll
                for (int nf = 0; nf < 8; ++nf)
                    mma_tf32(acc[mf][nf], af[mf], bf[nf]);
        }
    }

    // Fused epilogue: s[row] = sum_n p[b,n]*(C[b,n] + pb[o,n])
    const float* __restrict__ pbo = pb + (size_t)o * N_LEAF;
    #pragma unroll
    for (int mf = 0; mf < 2; ++mf) {
        const int r0 = wm * 32 + mf * 16 + lq;
        const int r1 = r0 + 8;
        const float* p0row = d_leafp + (size_t)(b0 + r0) * N_LEAF;
        const float* p1row = d_leafp + (size_t)(b0 + r1) * N_LEAF;
        float s0 = 0.0f, s1 = 0.0f;
        #pragma unroll
        for (int nf = 0; nf < 8; ++nf) {
            const int n = wn * 64 + nf * 8 + 2 * lr;
            float2 pbv = *reinterpret_cast<const float2*>(pbo + n);
            float2 pa  = *reinterpret_cast<const float2*>(p0row + n);
            float2 pc  = *reinterpret_cast<const float2*>(p1row + n);
            s0 = fmaf(acc[mf][nf][0] + pbv.x, pa.x, s0);
            s0 = fmaf(acc[mf][nf][1] + pbv.y, pa.y, s0);
            s1 = fmaf(acc[mf][nf][2] + pbv.x, pc.x, s1);
            s1 = fmaf(acc[mf][nf][3] + pbv.y, pc.y, s1);
        }
        s0 += __shfl_xor_sync(0xffffffffu, s0, 1);
        s0 += __shfl_xor_sync(0xffffffffu, s0, 2);
        s1 += __shfl_xor_sync(0xffffffffu, s1, 1);
        s1 += __shfl_xor_sync(0xffffffffu, s1, 2);
        if (lr == 0) {
            red[wn * 128 + r0] = s0;
            red[wn * 128 + r1] = s1;
        }
    }
    __syncthreads();

    if (tid < 128) {
        float v = red[0 * 128 + tid] + red[1 * 128 + tid] +
                  red[2 * 128 + tid] + red[3 * 128 + tid];
        out[(size_t)(b0 + tid) * N_OUT + o] = v;
    }
}

// ---------------------------------------------------------------------------
extern "C" void kernel_launch(void* const* d_in, const int* in_sizes, int n_in,
                              void* d_out, int out_size)
{
    const float* x  = (const float*)d_in[0];
    const float* gw = (const float*)d_in[1];
    const float* gb = (const float*)d_in[2];
    const float* pw = (const float*)d_in[3];
    const float* pb = (const float*)d_in[4];
    float* out = (float*)d_out;

    const int smem_bytes = SMEM_FLOATS * 4;     // 198,656 B
    cudaFuncSetAttribute(softtree_gemm_mma,
                         cudaFuncAttributeMaxDynamicSharedMemorySize, smem_bytes);

    xt2_kernel<<<dim3(16, 32), 256>>>(x);
    pwp_kernel<<<dim3(64, 64), 256>>>(pw);
    softtree_gates_kernel<<<N_BATCH / K1_ROWS, 256>>>(x, gw, gb);

    dim3 grid(N_BATCH / 128, N_OUT);
    softtree_gemm_mma<<<grid, 512, smem_bytes>>>(pb, out);
}

// round 10
// speedup vs baseline: 1.0548x; 1.0548x over previous
#include <cuda_runtime.h>
#include <cstdint>

// SoftTree: x[4096,512], gw[512,255], gb[255], pw[64,512,256], pb[64,256]
// out[b,o] = sum_l leafp[b,l] * ((x @ pw[o])[b,l] + pb[o,l])
//
// R10 vs R8: 2 independent CTAs per SM to cover stage-boundary bubbles.
// CTA tile 64x256 (4 warps, warp tile 64x64 = R8's proven feed ratio),
// __launch_bounds__(128,2), 2-stage 40KB ring, grid (64 bt, 64 o).
// Fragment-packed operands (d_xt2 quads / d_pwp pairs) unchanged from R8.

#define N_BATCH   4096
#define N_IN      512
#define N_OUT     64
#define N_LEAF    256
#define N_GATE    255
#define TREE_DEPTH 8

__device__ float  d_leafp[N_BATCH * N_LEAF];                 // 4 MB
__device__ float4 d_xt2[(N_BATCH / 128) * 16 * 1024];        // 8 MB  (A quads)
__device__ float2 d_pwp[(size_t)N_OUT * 16 * 4096];          // 33.5 MB (B pairs)

__device__ __forceinline__ float rna_tf32(float f) {
    uint32_t u;
    asm("cvt.rna.tf32.f32 %0, %1;" : "=r"(u) : "f"(f));
    return __uint_as_float(u);
}
__device__ __forceinline__ uint32_t smem_u32(const void* p) {
    uint32_t a;
    asm("{ .reg .u64 t; cvta.to.shared.u64 t, %1; cvt.u32.u64 %0, t; }"
        : "=r"(a) : "l"(p));
    return a;
}

#define CP_ASYNC16(dst_u32, src_ptr) \
    asm volatile("cp.async.cg.shared.global [%0], [%1], 16;" \
                 :: "r"(dst_u32), "l"(src_ptr))
#define CP_COMMIT()  asm volatile("cp.async.commit_group;" ::: "memory")
#define CP_WAIT1()   asm volatile("cp.async.wait_group 1;" ::: "memory")

__device__ __forceinline__ void mma_tf32(float* d, const uint32_t* a,
                                         const uint32_t* b) {
    asm volatile(
        "mma.sync.aligned.m16n8k8.row.col.f32.tf32.tf32.f32 "
        "{%0,%1,%2,%3}, {%4,%5,%6,%7}, {%8,%9}, {%0,%1,%2,%3};"
        : "+f"(d[0]), "+f"(d[1]), "+f"(d[2]), "+f"(d[3])
        : "r"(a[0]), "r"(a[1]), "r"(a[2]), "r"(a[3]), "r"(b[0]), "r"(b[1]));
}

// ---------------------------------------------------------------------------
// P0: x -> A-frag quads (layout keyed by 128-row blocks; 64-row CTAs use
// halves: quads [0,512) = rows 0..63, [512,1024) = rows 64..127).
//   float4 = { x[b][k], x[b+8][k], x[b][k+4], x[b+8][k+4] }  (rna)
//   linear = (bt128*16+kt)*1024 + (mb*4+ks)*32 + lq*4 + lr
// ---------------------------------------------------------------------------
__global__ __launch_bounds__(256) void xt2_kernel(const float* __restrict__ x) {
    const int kt = blockIdx.x, bt = blockIdx.y;
    #pragma unroll
    for (int it = 0; it < 4; ++it) {
        int qid = it * 256 + threadIdx.x;          // 0..1023
        int mb = qid >> 7, ks = (qid >> 5) & 3, lq = (qid >> 2) & 7, lr = qid & 3;
        int b = bt * 128 + mb * 16 + lq;
        int k = kt * 32 + ks * 8 + lr;
        const float* xb = x + (size_t)b * N_IN + k;
        float4 q;
        q.x = rna_tf32(xb[0]);
        q.y = rna_tf32(xb[8 * N_IN]);
        q.z = rna_tf32(xb[4]);
        q.w = rna_tf32(xb[8 * N_IN + 4]);
        d_xt2[(size_t)(bt * 16 + kt) * 1024 + qid] = q;
    }
}

// ---------------------------------------------------------------------------
// P1: pw -> B-frag pairs (coalesced 2x float4 stores).
//   float2 = { pw[o][kt*32+ks*8+lr][n], pw[o][kt*32+ks*8+lr+4][n] } (rna)
//   linear = ((o*16+kt)*4+ks)*1024 + n*4 + lr
// ---------------------------------------------------------------------------
__global__ __launch_bounds__(256) void pwp_kernel(const float* __restrict__ pw) {
    const int o = blockIdx.y;
    const int kt = blockIdx.x >> 2, ks = blockIdx.x & 3;
    const int n = threadIdx.x;
    const int k0 = kt * 32 + ks * 8;
    const float* src = pw + ((size_t)o * N_IN + k0) * N_LEAF + n;
    float v[8];
    #pragma unroll
    for (int j = 0; j < 8; ++j) v[j] = rna_tf32(src[j * N_LEAF]);
    float4* dst = reinterpret_cast<float4*>(
        d_pwp + ((size_t)(o * 16 + kt) * 4 + ks) * 1024 + n * 4);
    dst[0] = make_float4(v[0], v[4], v[1], v[5]);
    dst[1] = make_float4(v[2], v[6], v[3], v[7]);
}

// ---------------------------------------------------------------------------
// K2: gates + leaf probabilities (proven)
// ---------------------------------------------------------------------------
#define K1_ROWS 8
__global__ __launch_bounds__(256) void softtree_gates_kernel(
    const float* __restrict__ x, const float* __restrict__ gw,
    const float* __restrict__ gb)
{
    __shared__ float xs[K1_ROWS][N_IN];
    __shared__ float gs[K1_ROWS][N_LEAF];
    const int tid = threadIdx.x;
    const int b0  = blockIdx.x * K1_ROWS;

    {
        const float4* src = reinterpret_cast<const float4*>(x + (size_t)b0 * N_IN);
        float4* dst = reinterpret_cast<float4*>(&xs[0][0]);
        #pragma unroll
        for (int it = 0; it < (K1_ROWS * N_IN / 4) / 256; ++it)
            dst[it * 256 + tid] = src[it * 256 + tid];
    }
    __syncthreads();

    if (tid < N_GATE) {
        float acc[K1_ROWS];
        const float bias = gb[tid];
        #pragma unroll
        for (int r = 0; r < K1_ROWS; ++r) acc[r] = bias;
        #pragma unroll 4
        for (int i = 0; i < N_IN; ++i) {
            float w = gw[i * N_GATE + tid];
            #pragma unroll
            for (int r = 0; r < K1_ROWS; ++r)
                acc[r] = fmaf(xs[r][i], w, acc[r]);
        }
        #pragma unroll
        for (int r = 0; r < K1_ROWS; ++r)
            gs[r][tid] = 1.0f / (1.0f + expf(-acc[r]));
    }
    __syncthreads();

    const int l = tid;
    #pragma unroll
    for (int r = 0; r < K1_ROWS; ++r) {
        float p = 1.0f;
        int index = 1;
        #pragma unroll
        for (int j = 0; j < TREE_DEPTH; ++j) {
            int bit = (l >> (TREE_DEPTH - 1 - j)) & 1;
            float g = gs[r][index - 1];
            p *= bit ? (1.0f - g) : g;
            index = 2 * index + bit;
        }
        d_leafp[(size_t)(b0 + r) * N_LEAF + l] = p;
    }
}

// ---------------------------------------------------------------------------
// K3: tf32 mma.sync GEMM, 2 CTAs/SM, fragment-order smem, fused epilogue.
// Grid (64 bt64, 64 o), 128 threads (4 warps, 1m x 4n), warp tile 64x64.
// Stage = A 8KB (512 quads) + B 32KB; 2-stage ring, 2 barriers/stage.
// ---------------------------------------------------------------------------
#define A_STAGE_F  2048                 // floats (512 quads)
#define B_STAGE_F  8192
#define STAGE_FLOATS (A_STAGE_F + B_STAGE_F)   // 40 KB
#define N_STAGES 2
#define SMEM_FLOATS (N_STAGES * STAGE_FLOATS + 4 * 64)
#define N_KT 16

__global__ __launch_bounds__(128, 2) void softtree_gemm_mma(
    const float* __restrict__ pb, float* __restrict__ out)
{
    extern __shared__ float sm[];
    float* red = sm + N_STAGES * STAGE_FLOATS;   // [4][64]

    const int tid  = threadIdx.x;
    const int lane = tid & 31;
    const int wn   = tid >> 5;          // 0..3 -> 64-col group
    const int lq   = lane >> 2;         // 0..7
    const int lr   = lane & 3;          // 0..3
    const int o    = blockIdx.y;
    const int bt64 = blockIdx.x;
    const int b0   = bt64 * 64;

    // A quads: half of a 128-row block
    const float4* __restrict__ xa_all =
        d_xt2 + ((size_t)(bt64 >> 1) * 16) * 1024 + (bt64 & 1) * 512;
    const float2* __restrict__ bb_all = d_pwp + (size_t)o * 16 * 4096;

    auto load_stage = [&](int kt) {
        const int s = kt & (N_STAGES - 1);
        uint32_t a_base = smem_u32(sm + s * STAGE_FLOATS);
        uint32_t b_base = a_base + A_STAGE_F * 4;
        const float4* xa = xa_all + kt * 1024;
        const float2* bb = bb_all + kt * 4096;
        #pragma unroll
        for (int it = 0; it < 4; ++it) {
            int i = it * 128 + tid;                 // quad 0..511
            CP_ASYNC16(a_base + (uint32_t)i * 16, xa + i);
        }
        #pragma unroll
        for (int it = 0; it < 16; ++it) {
            int i = it * 128 + tid;                 // 16B granule = 2 pairs
            CP_ASYNC16(b_base + (uint32_t)i * 16, bb + i * 2);
        }
        CP_COMMIT();
    };

    float acc[4][8][4];
    #pragma unroll
    for (int mf = 0; mf < 4; ++mf)
        #pragma unroll
        for (int nf = 0; nf < 8; ++nf)
            #pragma unroll
            for (int e = 0; e < 4; ++e) acc[mf][nf][e] = 0.0f;

    load_stage(0);
    load_stage(1);

    for (int kt = 0; kt < N_KT; ++kt) {
        CP_WAIT1();          // stage kt landed (<=1 group pending)
        __syncthreads();

        const int s = kt & (N_STAGES - 1);
        const float* Asb = sm + s * STAGE_FLOATS;
        const float* Bsb = Asb + A_STAGE_F;

        #pragma unroll
        for (int ks = 0; ks < 4; ++ks) {
            uint32_t af[4][4], bf[8][2];
            #pragma unroll
            for (int mf = 0; mf < 4; ++mf) {
                float4 a4 = *reinterpret_cast<const float4*>(
                    Asb + ((size_t)((mf * 4 + ks) * 32 + lq * 4 + lr)) * 4);
                af[mf][0] = __float_as_uint(a4.x);
                af[mf][1] = __float_as_uint(a4.y);
                af[mf][2] = __float_as_uint(a4.z);
                af[mf][3] = __float_as_uint(a4.w);
            }
            #pragma unroll
            for (int nf = 0; nf < 8; ++nf) {
                const int n = wn * 64 + nf * 8 + lq;
                float2 b2 = *reinterpret_cast<const float2*>(
                    Bsb + ((size_t)((ks * 256 + n) * 4 + lr)) * 2);
                bf[nf][0] = __float_as_uint(b2.x);
                bf[nf][1] = __float_as_uint(b2.y);
            }
            #pragma unroll
            for (int mf = 0; mf < 4; ++mf)
                #pragma unroll
                for (int nf = 0; nf < 8; ++nf)
                    mma_tf32(acc[mf][nf], af[mf], bf[nf]);
        }

        __syncthreads();     // all warps done with stage kt buffer
        if (kt + 2 < N_KT) load_stage(kt + 2);
    }

    // Fused epilogue: s[row] = sum_n p[b,n]*(C[b,n] + pb[o,n])
    const float* __restrict__ pbo = pb + (size_t)o * N_LEAF;
    #pragma unroll
    for (int mf = 0; mf < 4; ++mf) {
        const int r0 = mf * 16 + lq;
        const int r1 = r0 + 8;
        const float* p0row = d_leafp + (size_t)(b0 + r0) * N_LEAF;
        const float* p1row = d_leafp + (size_t)(b0 + r1) * N_LEAF;
        float s0 = 0.0f, s1 = 0.0f;
        #pragma unroll
        for (int nf = 0; nf < 8; ++nf) {
            const int n = wn * 64 + nf * 8 + 2 * lr;
            float2 pbv = *reinterpret_cast<const float2*>(pbo + n);
            float2 pa  = *reinterpret_cast<const float2*>(p0row + n);
            float2 pc  = *reinterpret_cast<const float2*>(p1row + n);
            s0 = fmaf(acc[mf][nf][0] + pbv.x, pa.x, s0);
            s0 = fmaf(acc[mf][nf][1] + pbv.y, pa.y, s0);
            s1 = fmaf(acc[mf][nf][2] + pbv.x, pc.x, s1);
            s1 = fmaf(acc[mf][nf][3] + pbv.y, pc.y, s1);
        }
        s0 += __shfl_xor_sync(0xffffffffu, s0, 1);
        s0 += __shfl_xor_sync(0xffffffffu, s0, 2);
        s1 += __shfl_xor_sync(0xffffffffu, s1, 1);
        s1 += __shfl_xor_sync(0xffffffffu, s1, 2);
        if (lr == 0) {
            red[wn * 64 + r0] = s0;
            red[wn * 64 + r1] = s1;
        }
    }
    __syncthreads();

    if (tid < 64) {
        float v = red[0 * 64 + tid] + red[1 * 64 + tid] +
                  red[2 * 64 + tid] + red[3 * 64 + tid];
        out[(size_t)(b0 + tid) * N_OUT + o] = v;
    }
}

// ---------------------------------------------------------------------------
extern "C" void kernel_launch(void* const* d_in, const int* in_sizes, int n_in,
                              void* d_out, int out_size)
{
    const float* x  = (const float*)d_in[0];
    const float* gw = (const float*)d_in[1];
    const float* gb = (const float*)d_in[2];
    const float* pw = (const float*)d_in[3];
    const float* pb = (const float*)d_in[4];
    float* out = (float*)d_out;

    const int smem_bytes = SMEM_FLOATS * 4;     // 82,944 B per CTA
    cudaFuncSetAttribute(softtree_gemm_mma,
                         cudaFuncAttributeMaxDynamicSharedMemorySize, smem_bytes);

    xt2_kernel<<<dim3(16, 32), 256>>>(x);
    pwp_kernel<<<dim3(64, 64), 256>>>(pw);
    softtree_gates_kernel<<<N_BATCH / K1_ROWS, 256>>>(x, gw, gb);

    dim3 grid(N_BATCH / 64, N_OUT);
    softtree_gemm_mma<<<grid, 128, smem_bytes>>>(pb, out);
}

// round 12
// speedup vs baseline: 1.0705x; 1.0150x over previous
#include <cuda_runtime.h>
#include <cstdint>

// SoftTree: x[4096,512], gw[512,255], gb[255], pw[64,512,256], pb[64,256]
// out[b,o] = sum_l leafp[b,l] * ((x @ pw[o])[b,l] + pb[o,l])
//
// R12 = R11 resubmitted unchanged (R11 hit "container failed twice"; static
// audit found no hang/OOB/compile-risk — testing the infra-flake hypothesis
// with zero confounding code changes).
//
// R11 vs R10: combine R8 + R10 wins.
//  - GEMM: 2 CTAs/SM (64x256 tile, 4 warps, warp tile 64x64) AND a 4-stage
//    cp.async ring at BK=16: ONE barrier per stage, 3-stage prefetch horizon.
//    Stage = 20KB; 4 stages x 2 CTAs = 162KB smem/SM.
//  - Prep: xt2/pwp/gates fused into one grid-dispatched kernel (concurrent).

#define N_BATCH   4096
#define N_IN      512
#define N_OUT     64
#define N_LEAF    256
#define N_GATE    255
#define TREE_DEPTH 8

__device__ float  d_leafp[N_BATCH * N_LEAF];                 // 4 MB
__device__ float4 d_xt2[(N_BATCH / 128) * 16 * 1024];        // 8 MB  (A quads)
__device__ float2 d_pwp[(size_t)N_OUT * 16 * 4096];          // 33.5 MB (B pairs)

__device__ __forceinline__ float rna_tf32(float f) {
    uint32_t u;
    asm("cvt.rna.tf32.f32 %0, %1;" : "=r"(u) : "f"(f));
    return __uint_as_float(u);
}
__device__ __forceinline__ uint32_t smem_u32(const void* p) {
    uint32_t a;
    asm("{ .reg .u64 t; cvta.to.shared.u64 t, %1; cvt.u32.u64 %0, t; }"
        : "=r"(a) : "l"(p));
    return a;
}

#define CP_ASYNC16(dst_u32, src_ptr) \
    asm volatile("cp.async.cg.shared.global [%0], [%1], 16;" \
                 :: "r"(dst_u32), "l"(src_ptr))
#define CP_COMMIT()  asm volatile("cp.async.commit_group;" ::: "memory")
#define CP_WAIT2()   asm volatile("cp.async.wait_group 2;" ::: "memory")

__device__ __forceinline__ void mma_tf32(float* d, const uint32_t* a,
                                         const uint32_t* b) {
    asm volatile(
        "mma.sync.aligned.m16n8k8.row.col.f32.tf32.tf32.f32 "
        "{%0,%1,%2,%3}, {%4,%5,%6,%7}, {%8,%9}, {%0,%1,%2,%3};"
        : "+f"(d[0]), "+f"(d[1]), "+f"(d[2]), "+f"(d[3])
        : "r"(a[0]), "r"(a[1]), "r"(a[2]), "r"(a[3]), "r"(b[0]), "r"(b[1]));
}

// ---------------------------------------------------------------------------
// Fused prep kernel (grid-dispatched, all parts independent & concurrent):
//  blocks [0,512):      xt2   (kt = blk&15, bt = blk>>4)
//  blocks [512,4608):   pwp   (idx: o = idx>>6; kt = (idx&63)>>2; ks = idx&3)
//  blocks [4608,5120):  gates (b-block = blk-4608)
// ---------------------------------------------------------------------------
#define K1_ROWS 8

__global__ __launch_bounds__(256) void softtree_prep_kernel(
    const float* __restrict__ x, const float* __restrict__ pw,
    const float* __restrict__ gw, const float* __restrict__ gb)
{
    const int blk = blockIdx.x;
    const int tid = threadIdx.x;

    if (blk < 512) {
        // ---- xt2: x -> A-frag quads ----
        // quad (bt,kt,mb,ks,lq,lr): rows b=bt*128+mb*16+lq(+8),
        // cols k=kt*32+ks*8+lr(+4); linear=(bt*16+kt)*1024+(mb*4+ks)*32+lq*4+lr
        const int kt = blk & 15, bt = blk >> 4;
        #pragma unroll
        for (int it = 0; it < 4; ++it) {
            int qid = it * 256 + tid;
            int mb = qid >> 7, ks = (qid >> 5) & 3, lq = (qid >> 2) & 7, lr = qid & 3;
            int b = bt * 128 + mb * 16 + lq;
            int k = kt * 32 + ks * 8 + lr;
            const float* xb = x + (size_t)b * N_IN + k;
            float4 q;
            q.x = rna_tf32(xb[0]);
            q.y = rna_tf32(xb[8 * N_IN]);
            q.z = rna_tf32(xb[4]);
            q.w = rna_tf32(xb[8 * N_IN + 4]);
            d_xt2[(size_t)(bt * 16 + kt) * 1024 + qid] = q;
        }
    } else if (blk < 4608) {
        // ---- pwp: pw -> B-frag pairs (coalesced 2x float4 stores) ----
        const int idx = blk - 512;
        const int o = idx >> 6;
        const int kt = (idx & 63) >> 2, ks = idx & 3;
        const int n = tid;
        const int k0 = kt * 32 + ks * 8;
        const float* src = pw + ((size_t)o * N_IN + k0) * N_LEAF + n;
        float v[8];
        #pragma unroll
        for (int j = 0; j < 8; ++j) v[j] = rna_tf32(src[j * N_LEAF]);
        float4* dst = reinterpret_cast<float4*>(
            d_pwp + ((size_t)(o * 16 + kt) * 4 + ks) * 1024 + n * 4);
        dst[0] = make_float4(v[0], v[4], v[1], v[5]);
        dst[1] = make_float4(v[2], v[6], v[3], v[7]);
    } else {
        // ---- gates + leaf probabilities ----
        __shared__ float xs[K1_ROWS][N_IN];
        __shared__ float gs[K1_ROWS][N_LEAF];
        const int b0 = (blk - 4608) * K1_ROWS;

        {
            const float4* src = reinterpret_cast<const float4*>(x + (size_t)b0 * N_IN);
            float4* dst = reinterpret_cast<float4*>(&xs[0][0]);
            #pragma unroll
            for (int it = 0; it < (K1_ROWS * N_IN / 4) / 256; ++it)
                dst[it * 256 + tid] = src[it * 256 + tid];
        }
        __syncthreads();

        if (tid < N_GATE) {
            float acc[K1_ROWS];
            const float bias = gb[tid];
            #pragma unroll
            for (int r = 0; r < K1_ROWS; ++r) acc[r] = bias;
            #pragma unroll 4
            for (int i = 0; i < N_IN; ++i) {
                float w = gw[i * N_GATE + tid];
                #pragma unroll
                for (int r = 0; r < K1_ROWS; ++r)
                    acc[r] = fmaf(xs[r][i], w, acc[r]);
            }
            #pragma unroll
            for (int r = 0; r < K1_ROWS; ++r)
                gs[r][tid] = 1.0f / (1.0f + expf(-acc[r]));
        }
        __syncthreads();

        const int l = tid;
        #pragma unroll
        for (int r = 0; r < K1_ROWS; ++r) {
            float p = 1.0f;
            int index = 1;
            #pragma unroll
            for (int j = 0; j < TREE_DEPTH; ++j) {
                int bit = (l >> (TREE_DEPTH - 1 - j)) & 1;
                float g = gs[r][index - 1];
                p *= bit ? (1.0f - g) : g;
                index = 2 * index + bit;
            }
            d_leafp[(size_t)(b0 + r) * N_LEAF + l] = p;
        }
    }
}

// ---------------------------------------------------------------------------
// GEMM: tf32 mma.sync, 2 CTAs/SM, BK=16, 4-stage ring, 1 barrier/stage.
// Grid (64 bt64, 64 o), 128 threads (4 warps, 1m x 4n), warp tile 64x64.
// Stage = A 4KB (256 quads) + B 16KB (2048 pairs) = 20KB.
// Stage st covers k in [st*16, st*16+16): kt32 = st>>1, half h = st&1,
// ks = 2h + ks2 (ks2 in {0,1}).
// Smem A layout: quad(mb, ks2, inner=lq*4+lr) at mb*64 + ks2*32 + inner.
// Smem B layout: pair(ks2, n, lr) at ks2*1024 + n*4 + lr (gmem-contiguous).
// ---------------------------------------------------------------------------
#define A_ST_F  1024                 // floats (256 quads)
#define B_ST_F  4096                 // floats (2048 pairs)
#define ST_F    (A_ST_F + B_ST_F)    // 20 KB
#define N_STAGES 4
#define SMEM_FLOATS (N_STAGES * ST_F + 4 * 64)
#define N_KT 32

__global__ __launch_bounds__(128, 2) void softtree_gemm_mma(
    const float* __restrict__ pb, float* __restrict__ out)
{
    extern __shared__ float sm[];
    float* red = sm + N_STAGES * ST_F;   // [4][64]

    const int tid  = threadIdx.x;
    const int lane = tid & 31;
    const int wn   = tid >> 5;          // 0..3 -> 64-col group
    const int lq   = lane >> 2;         // 0..7
    const int lr   = lane & 3;          // 0..3
    const int o    = blockIdx.y;
    const int bt64 = blockIdx.x;
    const int b0   = bt64 * 64;

    const float4* __restrict__ xa_all =
        d_xt2 + ((size_t)(bt64 >> 1) * 16) * 1024 + (bt64 & 1) * 512;
    const float2* __restrict__ bb_all = d_pwp + (size_t)o * 16 * 4096;

    auto load_stage = [&](int st) {
        const int s = st & (N_STAGES - 1);
        const int kt32 = st >> 1, h = st & 1;
        uint32_t a_base = smem_u32(sm + s * ST_F);
        uint32_t b_base = a_base + A_ST_F * 4;
        const float4* xa = xa_all + kt32 * 1024;
        const float2* bb = bb_all + (size_t)(kt32 * 4 + 2 * h) * 1024;
        #pragma unroll
        for (int it = 0; it < 2; ++it) {
            int q = it * 128 + tid;                 // 0..255 (smem quad id)
            int mb = q >> 6, ks2 = (q >> 5) & 1, inner = q & 31;
            int qg = (mb * 4 + 2 * h + ks2) * 32 + inner;
            CP_ASYNC16(a_base + (uint32_t)q * 16, xa + qg);
        }
        #pragma unroll
        for (int it = 0; it < 8; ++it) {
            int i = it * 128 + tid;                 // 16B granule = 2 pairs
            CP_ASYNC16(b_base + (uint32_t)i * 16, bb + i * 2);
        }
        CP_COMMIT();
    };

    float acc[4][8][4];
    #pragma unroll
    for (int mf = 0; mf < 4; ++mf)
        #pragma unroll
        for (int nf = 0; nf < 8; ++nf)
            #pragma unroll
            for (int e = 0; e < 4; ++e) acc[mf][nf][e] = 0.0f;

    load_stage(0);
    load_stage(1);
    load_stage(2);

    for (int st = 0; st < N_KT; ++st) {
        CP_WAIT2();          // stage st landed (<=2 groups pending)
        __syncthreads();
        if (st + 3 < N_KT) load_stage(st + 3);  // buffer (st-1)&3: free

        const int s = st & (N_STAGES - 1);
        const float* Asb = sm + s * ST_F;
        const float* Bsb = Asb + A_ST_F;

        #pragma unroll
        for (int ks2 = 0; ks2 < 2; ++ks2) {
            uint32_t af[4][4], bf[8][2];
            #pragma unroll
            for (int mf = 0; mf < 4; ++mf) {
                float4 a4 = *reinterpret_cast<const float4*>(
                    Asb + ((size_t)(mf * 64 + ks2 * 32 + lq * 4 + lr)) * 4);
                af[mf][0] = __float_as_uint(a4.x);
                af[mf][1] = __float_as_uint(a4.y);
                af[mf][2] = __float_as_uint(a4.z);
                af[mf][3] = __float_as_uint(a4.w);
            }
            #pragma unroll
            for (int nf = 0; nf < 8; ++nf) {
                const int n = wn * 64 + nf * 8 + lq;
                float2 b2 = *reinterpret_cast<const float2*>(
                    Bsb + ((size_t)(ks2 * 1024 + n * 4 + lr)) * 2);
                bf[nf][0] = __float_as_uint(b2.x);
                bf[nf][1] = __float_as_uint(b2.y);
            }
            #pragma unroll
            for (int mf = 0; mf < 4; ++mf)
                #pragma unroll
                for (int nf = 0; nf < 8; ++nf)
                    mma_tf32(acc[mf][nf], af[mf], bf[nf]);
        }
    }

    // Fused epilogue: s[row] = sum_n p[b,n]*(C[b,n] + pb[o,n])
    const float* __restrict__ pbo = pb + (size_t)o * N_LEAF;
    #pragma unroll
    for (int mf = 0; mf < 4; ++mf) {
        const int r0 = mf * 16 + lq;
        const int r1 = r0 + 8;
        const float* p0row = d_leafp + (size_t)(b0 + r0) * N_LEAF;
        const float* p1row = d_leafp + (size_t)(b0 + r1) * N_LEAF;
        float s0 = 0.0f, s1 = 0.0f;
        #pragma unroll
        for (int nf = 0; nf < 8; ++nf) {
            const int n = wn * 64 + nf * 8 + 2 * lr;
            float2 pbv = *reinterpret_cast<const float2*>(pbo + n);
            float2 pa  = *reinterpret_cast<const float2*>(p0row + n);
            float2 pc  = *reinterpret_cast<const float2*>(p1row + n);
            s0 = fmaf(acc[mf][nf][0] + pbv.x, pa.x, s0);
            s0 = fmaf(acc[mf][nf][1] + pbv.y, pa.y, s0);
            s1 = fmaf(acc[mf][nf][2] + pbv.x, pc.x, s1);
            s1 = fmaf(acc[mf][nf][3] + pbv.y, pc.y, s1);
        }
        s0 += __shfl_xor_sync(0xffffffffu, s0, 1);
        s0 += __shfl_xor_sync(0xffffffffu, s0, 2);
        s1 += __shfl_xor_sync(0xffffffffu, s1, 1);
        s1 += __shfl_xor_sync(0xffffffffu, s1, 2);
        if (lr == 0) {
            red[wn * 64 + r0] = s0;
            red[wn * 64 + r1] = s1;
        }
    }
    __syncthreads();

    if (tid < 64) {
        float v = red[0 * 64 + tid] + red[1 * 64 + tid] +
                  red[2 * 64 + tid] + red[3 * 64 + tid];
        out[(size_t)(b0 + tid) * N_OUT + o] = v;
    }
}

// ---------------------------------------------------------------------------
extern "C" void kernel_launch(void* const* d_in, const int* in_sizes, int n_in,
                              void* d_out, int out_size)
{
    const float* x  = (const float*)d_in[0];
    const float* gw = (const float*)d_in[1];
    const float* gb = (const float*)d_in[2];
    const float* pw = (const float*)d_in[3];
    const float* pb = (const float*)d_in[4];
    float* out = (float*)d_out;

    const int smem_bytes = SMEM_FLOATS * 4;     // 82,944 B per CTA
    cudaFuncSetAttribute(softtree_gemm_mma,
                         cudaFuncAttributeMaxDynamicSharedMemorySize, smem_bytes);

    softtree_prep_kernel<<<5120, 256>>>(x, pw, gw, gb);

    dim3 grid(N_BATCH / 64, N_OUT);
    softtree_gemm_mma<<<grid, 128, smem_bytes>>>(pb, out);
}

// round 13
// speedup vs baseline: 1.1267x; 1.0524x over previous
#include <cuda_runtime.h>
#include <cstdint>

// SoftTree: x[4096,512], gw[512,255], gb[255], pw[64,512,256], pb[64,256]
// out[b,o] = sum_l leafp[b,l] * ((x @ pw[o])[b,l] + pb[o,l])
//
// R13 vs R12:
//  - GEMM main loop unrolled by 4 stages: ring slot + half-index h are
//    compile-time, loader addressing is pointer+const (alu 10.4% -> ~5%).
//  - Prep back to 3 separate kernels (fused prep measured ~18us slower).
// GEMM config unchanged: 2 CTAs/SM, 64x256 tile, 4 warps, warp tile 64x64,
// BK=16, 4-stage cp.async ring, 1 barrier/stage, fragment-packed operands.

#define N_BATCH   4096
#define N_IN      512
#define N_OUT     64
#define N_LEAF    256
#define N_GATE    255
#define TREE_DEPTH 8

__device__ float  d_leafp[N_BATCH * N_LEAF];                 // 4 MB
__device__ float4 d_xt2[(N_BATCH / 128) * 16 * 1024];        // 8 MB  (A quads)
__device__ float2 d_pwp[(size_t)N_OUT * 16 * 4096];          // 33.5 MB (B pairs)

__device__ __forceinline__ float rna_tf32(float f) {
    uint32_t u;
    asm("cvt.rna.tf32.f32 %0, %1;" : "=r"(u) : "f"(f));
    return __uint_as_float(u);
}
__device__ __forceinline__ uint32_t smem_u32(const void* p) {
    uint32_t a;
    asm("{ .reg .u64 t; cvta.to.shared.u64 t, %1; cvt.u32.u64 %0, t; }"
        : "=r"(a) : "l"(p));
    return a;
}

#define CP_ASYNC16(dst_u32, src_ptr) \
    asm volatile("cp.async.cg.shared.global [%0], [%1], 16;" \
                 :: "r"(dst_u32), "l"(src_ptr))
#define CP_COMMIT()  asm volatile("cp.async.commit_group;" ::: "memory")
#define CP_WAIT2()   asm volatile("cp.async.wait_group 2;" ::: "memory")

__device__ __forceinline__ void mma_tf32(float* d, const uint32_t* a,
                                         const uint32_t* b) {
    asm volatile(
        "mma.sync.aligned.m16n8k8.row.col.f32.tf32.tf32.f32 "
        "{%0,%1,%2,%3}, {%4,%5,%6,%7}, {%8,%9}, {%0,%1,%2,%3};"
        : "+f"(d[0]), "+f"(d[1]), "+f"(d[2]), "+f"(d[3])
        : "r"(a[0]), "r"(a[1]), "r"(a[2]), "r"(a[3]), "r"(b[0]), "r"(b[1]));
}

// ---------------------------------------------------------------------------
// P0: x -> A-frag quads.
//   quad (bt,kt,mb,ks,lq,lr): rows b=bt*128+mb*16+lq(+8),
//   cols k=kt*32+ks*8+lr(+4); linear=(bt*16+kt)*1024+(mb*4+ks)*32+lq*4+lr
// ---------------------------------------------------------------------------
__global__ __launch_bounds__(256) void xt2_kernel(const float* __restrict__ x) {
    const int kt = blockIdx.x, bt = blockIdx.y;
    #pragma unroll
    for (int it = 0; it < 4; ++it) {
        int qid = it * 256 + threadIdx.x;
        int mb = qid >> 7, ks = (qid >> 5) & 3, lq = (qid >> 2) & 7, lr = qid & 3;
        int b = bt * 128 + mb * 16 + lq;
        int k = kt * 32 + ks * 8 + lr;
        const float* xb = x + (size_t)b * N_IN + k;
        float4 q;
        q.x = rna_tf32(xb[0]);
        q.y = rna_tf32(xb[8 * N_IN]);
        q.z = rna_tf32(xb[4]);
        q.w = rna_tf32(xb[8 * N_IN + 4]);
        d_xt2[(size_t)(bt * 16 + kt) * 1024 + qid] = q;
    }
}

// ---------------------------------------------------------------------------
// P1: pw -> B-frag pairs (coalesced 2x float4 stores).
//   pair (o,kt,ks,n,lr): {pw[o][kt*32+ks*8+lr][n], pw[o][...+lr+4][n]} (rna)
//   linear = ((o*16+kt)*4+ks)*1024 + n*4 + lr
// ---------------------------------------------------------------------------
__global__ __launch_bounds__(256) void pwp_kernel(const float* __restrict__ pw) {
    const int o = blockIdx.y;
    const int kt = blockIdx.x >> 2, ks = blockIdx.x & 3;
    const int n = threadIdx.x;
    const int k0 = kt * 32 + ks * 8;
    const float* src = pw + ((size_t)o * N_IN + k0) * N_LEAF + n;
    float v[8];
    #pragma unroll
    for (int j = 0; j < 8; ++j) v[j] = rna_tf32(src[j * N_LEAF]);
    float4* dst = reinterpret_cast<float4*>(
        d_pwp + ((size_t)(o * 16 + kt) * 4 + ks) * 1024 + n * 4);
    dst[0] = make_float4(v[0], v[4], v[1], v[5]);
    dst[1] = make_float4(v[2], v[6], v[3], v[7]);
}

// ---------------------------------------------------------------------------
// K2: gates + leaf probabilities (proven)
// ---------------------------------------------------------------------------
#define K1_ROWS 8
__global__ __launch_bounds__(256) void softtree_gates_kernel(
    const float* __restrict__ x, const float* __restrict__ gw,
    const float* __restrict__ gb)
{
    __shared__ float xs[K1_ROWS][N_IN];
    __shared__ float gs[K1_ROWS][N_LEAF];
    const int tid = threadIdx.x;
    const int b0  = blockIdx.x * K1_ROWS;

    {
        const float4* src = reinterpret_cast<const float4*>(x + (size_t)b0 * N_IN);
        float4* dst = reinterpret_cast<float4*>(&xs[0][0]);
        #pragma unroll
        for (int it = 0; it < (K1_ROWS * N_IN / 4) / 256; ++it)
            dst[it * 256 + tid] = src[it * 256 + tid];
    }
    __syncthreads();

    if (tid < N_GATE) {
        float acc[K1_ROWS];
        const float bias = gb[tid];
        #pragma unroll
        for (int r = 0; r < K1_ROWS; ++r) acc[r] = bias;
        #pragma unroll 4
        for (int i = 0; i < N_IN; ++i) {
            float w = gw[i * N_GATE + tid];
            #pragma unroll
            for (int r = 0; r < K1_ROWS; ++r)
                acc[r] = fmaf(xs[r][i], w, acc[r]);
        }
        #pragma unroll
        for (int r = 0; r < K1_ROWS; ++r)
            gs[r][tid] = 1.0f / (1.0f + expf(-acc[r]));
    }
    __syncthreads();

    const int l = tid;
    #pragma unroll
    for (int r = 0; r < K1_ROWS; ++r) {
        float p = 1.0f;
        int index = 1;
        #pragma unroll
        for (int j = 0; j < TREE_DEPTH; ++j) {
            int bit = (l >> (TREE_DEPTH - 1 - j)) & 1;
            float g = gs[r][index - 1];
            p *= bit ? (1.0f - g) : g;
            index = 2 * index + bit;
        }
        d_leafp[(size_t)(b0 + r) * N_LEAF + l] = p;
    }
}

// ---------------------------------------------------------------------------
// GEMM: tf32 mma.sync, 2 CTAs/SM, BK=16, 4-stage ring, 1 barrier/stage,
// main loop unrolled by 4 stages (slot + h compile-time).
// Grid (64 bt64, 64 o), 128 threads (4 warps, 1m x 4n), warp tile 64x64.
// Smem A: quad(mb,ks2,inner) at mb*64+ks2*32+inner. B: gmem-contiguous.
// ---------------------------------------------------------------------------
#define A_ST_F  1024
#define B_ST_F  4096
#define ST_F    (A_ST_F + B_ST_F)
#define N_STAGES 4
#define SMEM_FLOATS (N_STAGES * ST_F + 4 * 64)

template <int H>
__device__ __forceinline__ void load_stage_t(
    uint32_t a_base, uint32_t b_base,
    const float4* __restrict__ xa, const float2* __restrict__ bb, int tid)
{
    #pragma unroll
    for (int it = 0; it < 2; ++it) {
        int q = it * 128 + tid;                 // smem quad 0..255
        int mb = q >> 6, ks2 = (q >> 5) & 1, inner = q & 31;
        int qg = (mb * 4 + 2 * H + ks2) * 32 + inner;
        CP_ASYNC16(a_base + (uint32_t)q * 16, xa + qg);
    }
    #pragma unroll
    for (int it = 0; it < 8; ++it) {
        int i = it * 128 + tid;
        CP_ASYNC16(b_base + (uint32_t)i * 16, bb + i * 2);
    }
    CP_COMMIT();
}

__global__ __launch_bounds__(128, 2) void softtree_gemm_mma(
    const float* __restrict__ pb, float* __restrict__ out)
{
    extern __shared__ float sm[];
    float* red = sm + N_STAGES * ST_F;   // [4][64]

    const int tid  = threadIdx.x;
    const int lane = tid & 31;
    const int wn   = tid >> 5;
    const int lq   = lane >> 2;
    const int lr   = lane & 3;
    const int o    = blockIdx.y;
    const int bt64 = blockIdx.x;
    const int b0   = bt64 * 64;

    const float4* __restrict__ xa_all =
        d_xt2 + ((size_t)(bt64 >> 1) * 16) * 1024 + (bt64 & 1) * 512;
    const float2* __restrict__ bb_all = d_pwp + (size_t)o * 16 * 4096;

    const uint32_t smb = smem_u32(sm);
    const uint32_t ab0 = smb + 0 * ST_F * 4, bb0 = ab0 + A_ST_F * 4;
    const uint32_t ab1 = smb + 1 * ST_F * 4, bb1 = ab1 + A_ST_F * 4;
    const uint32_t ab2 = smb + 2 * ST_F * 4, bb2 = ab2 + A_ST_F * 4;
    const uint32_t ab3 = smb + 3 * ST_F * 4, bb3 = ab3 + A_ST_F * 4;

    float acc[4][8][4];
    #pragma unroll
    for (int mf = 0; mf < 4; ++mf)
        #pragma unroll
        for (int nf = 0; nf < 8; ++nf)
            #pragma unroll
            for (int e = 0; e < 4; ++e) acc[mf][nf][e] = 0.0f;

    // compute on ring slot (A at a_sm floats, B at a_sm + A_ST_F)
    auto compute_stage = [&](const float* Asb) {
        const float* Bsb = Asb + A_ST_F;
        #pragma unroll
        for (int ks2 = 0; ks2 < 2; ++ks2) {
            uint32_t af[4][4], bf[8][2];
            #pragma unroll
            for (int mf = 0; mf < 4; ++mf) {
                float4 a4 = *reinterpret_cast<const float4*>(
                    Asb + ((size_t)(mf * 64 + ks2 * 32 + lq * 4 + lr)) * 4);
                af[mf][0] = __float_as_uint(a4.x);
                af[mf][1] = __float_as_uint(a4.y);
                af[mf][2] = __float_as_uint(a4.z);
                af[mf][3] = __float_as_uint(a4.w);
            }
            #pragma unroll
            for (int nf = 0; nf < 8; ++nf) {
                const int n = wn * 64 + nf * 8 + lq;
                float2 b2 = *reinterpret_cast<const float2*>(
                    Bsb + ((size_t)(ks2 * 1024 + n * 4 + lr)) * 2);
                bf[nf][0] = __float_as_uint(b2.x);
                bf[nf][1] = __float_as_uint(b2.y);
            }
            #pragma unroll
            for (int mf = 0; mf < 4; ++mf)
                #pragma unroll
                for (int nf = 0; nf < 8; ++nf)
                    mma_tf32(acc[mf][nf], af[mf], bf[nf]);
        }
    };

    // Prologue: stages 0 (slot0,h0), 1 (slot1,h1), 2 (slot2,h0)
    load_stage_t<0>(ab0, bb0, xa_all,        bb_all,        tid);
    load_stage_t<1>(ab1, bb1, xa_all,        bb_all + 2048, tid);
    load_stage_t<0>(ab2, bb2, xa_all + 1024, bb_all + 4096, tid);

    // Main loop: 8 groups of 4 stages (4q..4q+3 -> slots 0..3).
    #pragma unroll 1
    for (int q = 0; q < 8; ++q) {
        const float4* xaq = xa_all + (size_t)(2 * q) * 1024;
        const float2* bbq = bb_all + (size_t)(4 * q) * 2048;

        // stage 4q (slot 0): prefetch 4q+3 (slot 3, h=1, kt32=2q+1)
        CP_WAIT2(); __syncthreads();
        load_stage_t<1>(ab3, bb3, xaq + 1024, bbq + 3 * 2048, tid);
        compute_stage(sm + 0 * ST_F);

        // stage 4q+1 (slot 1): prefetch 4q+4 (slot 0, h=0, kt32=2q+2)
        CP_WAIT2(); __syncthreads();
        if (q < 7)
            load_stage_t<0>(ab0, bb0, xaq + 2048, bbq + 4 * 2048, tid);
        compute_stage(sm + 1 * ST_F);

        // stage 4q+2 (slot 2): prefetch 4q+5 (slot 1, h=1, kt32=2q+2)
        CP_WAIT2(); __syncthreads();
        if (q < 7)
            load_stage_t<1>(ab1, bb1, xaq + 2048, bbq + 5 * 2048, tid);
        compute_stage(sm + 2 * ST_F);

        // stage 4q+3 (slot 3): prefetch 4q+6 (slot 2, h=0, kt32=2q+3)
        CP_WAIT2(); __syncthreads();
        if (q < 7)
            load_stage_t<0>(ab2, bb2, xaq + 3072, bbq + 6 * 2048, tid);
        compute_stage(sm + 3 * ST_F);
    }

    // Fused epilogue: s[row] = sum_n p[b,n]*(C[b,n] + pb[o,n])
    const float* __restrict__ pbo = pb + (size_t)o * N_LEAF;
    #pragma unroll
    for (int mf = 0; mf < 4; ++mf) {
        const int r0 = mf * 16 + lq;
        const int r1 = r0 + 8;
        const float* p0row = d_leafp + (size_t)(b0 + r0) * N_LEAF;
        const float* p1row = d_leafp + (size_t)(b0 + r1) * N_LEAF;
        float s0 = 0.0f, s1 = 0.0f;
        #pragma unroll
        for (int nf = 0; nf < 8; ++nf) {
            const int n = wn * 64 + nf * 8 + 2 * lr;
            float2 pbv = *reinterpret_cast<const float2*>(pbo + n);
            float2 pa  = *reinterpret_cast<const float2*>(p0row + n);
            float2 pc  = *reinterpret_cast<const float2*>(p1row + n);
            s0 = fmaf(acc[mf][nf][0] + pbv.x, pa.x, s0);
            s0 = fmaf(acc[mf][nf][1] + pbv.y, pa.y, s0);
            s1 = fmaf(acc[mf][nf][2] + pbv.x, pc.x, s1);
            s1 = fmaf(acc[mf][nf][3] + pbv.y, pc.y, s1);
        }
        s0 += __shfl_xor_sync(0xffffffffu, s0, 1);
        s0 += __shfl_xor_sync(0xffffffffu, s0, 2);
        s1 += __shfl_xor_sync(0xffffffffu, s1, 1);
        s1 += __shfl_xor_sync(0xffffffffu, s1, 2);
        if (lr == 0) {
            red[wn * 64 + r0] = s0;
            red[wn * 64 + r1] = s1;
        }
    }
    __syncthreads();

    if (tid < 64) {
        float v = red[0 * 64 + tid] + red[1 * 64 + tid] +
                  red[2 * 64 + tid] + red[3 * 64 + tid];
        out[(size_t)(b0 + tid) * N_OUT + o] = v;
    }
}

// ---------------------------------------------------------------------------
extern "C" void kernel_launch(void* const* d_in, const int* in_sizes, int n_in,
                              void* d_out, int out_size)
{
    const float* x  = (const float*)d_in[0];
    const float* gw = (const float*)d_in[1];
    const float* gb = (const float*)d_in[2];
    const float* pw = (const float*)d_in[3];
    const float* pb = (const float*)d_in[4];
    float* out = (float*)d_out;

    const int smem_bytes = SMEM_FLOATS * 4;     // 82,944 B per CTA
    cudaFuncSetAttribute(softtree_gemm_mma,
                         cudaFuncAttributeMaxDynamicSharedMemorySize, smem_bytes);

    xt2_kernel<<<dim3(16, 32), 256>>>(x);
    pwp_kernel<<<dim3(64, 64), 256>>>(pw);
    softtree_gates_kernel<<<N_BATCH / K1_ROWS, 256>>>(x, gw, gb);

    dim3 grid(N_BATCH / 64, N_OUT);
    softtree_gemm_mma<<<grid, 128, smem_bytes>>>(pb, out);
}